// round 2
// baseline (speedup 1.0000x reference)
#include <cuda_runtime.h>
#include <cuda_bf16.h>
#include <cstdint>

// ---------------------------------------------------------------------------
// SparseConvNeXtBlock: dwconv7x7 -> LN(C) -> [mask-gated] MLP(384->1536->384,
// exact GELU) -> *gamma -> mask -> +x.   B=16, C=384, H=W=56.
// Mask gates aligned 8x8 spatial blocks (784 groups of 64 tokens).
// ---------------------------------------------------------------------------

namespace {
constexpr int Bn = 16, Cn = 384, Hn = 56, Wn = 56, HID = 1536;
constexpr int NGRP = 784;              // Bn * 7 * 7
constexpr int TOKENS = Bn * Hn * Wn;   // 50176
constexpr float EPSV = 1e-6f;
}

// Scratch (static device globals; no runtime allocation allowed)
__device__ __nv_bfloat16 g_yconv[TOKENS * Cn];   // conv+bias, NHWC, bf16
__device__ __nv_bfloat16 g_xc[TOKENS * Cn];      // compacted LN output
__device__ __nv_bfloat16 g_h[TOKENS * HID];      // compacted hidden (post-GELU)
__device__ __nv_bfloat16 g_w1[Cn * HID];
__device__ __nv_bfloat16 g_w2[HID * Cn];
__device__ int g_active[NGRP];
__device__ int g_list[NGRP];
__device__ int g_slot[NGRP];
__device__ int g_count;

__device__ __forceinline__ float geluf(float v) {
    return 0.5f * v * (1.0f + erff(v * 0.70710678118654752f));
}

// ---------------------------------------------------------------------------
// Mask decode: mask is logically bool[784]; dtype on the wire may be uint8,
// int32, or float32. Detect from byte patterns (reads only the guaranteed
// 784 bytes unless the pattern proves a wider dtype).
// ---------------------------------------------------------------------------
__global__ void k_decode_mask(const unsigned char* __restrict__ m) {
    __shared__ int c1s, c2s, c3s, mode;
    if (threadIdx.x == 0) { c1s = 0; c2s = 0; c3s = 0; }
    __syncthreads();
    int l1 = 0, l2 = 0, l3 = 0;
    for (int i = threadIdx.x; i < NGRP; i += blockDim.x) {
        unsigned char v = m[i];
        if (v > 1) l1 = 1;
        if ((i & 3) != 0 && v != 0) l2 = 1;
        if (v != 0) l3 = 1;
    }
    if (l1) atomicOr(&c1s, 1);
    if (l2) atomicOr(&c2s, 1);
    if (l3) atomicOr(&c3s, 1);
    __syncthreads();
    if (threadIdx.x == 0) mode = c1s ? 2 : (c2s ? 0 : (c3s ? 1 : 0));
    __syncthreads();
    int md = mode;
    for (int i = threadIdx.x; i < NGRP; i += blockDim.x) {
        int a;
        if (md == 0)      a = (m[i] != 0);
        else if (md == 1) a = (((const int*)m)[i] != 0);
        else              a = (((const float*)m)[i] != 0.0f);
        g_active[i] = a;
    }
}

// Deterministic compaction of active groups (single block).
__global__ void k_compact() {
    __shared__ int act[NGRP];
    int t = threadIdx.x;
    for (int i = t; i < NGRP; i += blockDim.x) act[i] = g_active[i];
    __syncthreads();
    if (t < NGRP) {
        int s = 0;
        for (int j = 0; j < t; j++) s += act[j];
        if (act[t]) { g_list[s] = t; g_slot[t] = s; }
        else        { g_slot[t] = -1; }
    }
    if (t == 0) {
        int tot = 0;
        for (int j = 0; j < NGRP; j++) tot += act[j];
        g_count = tot;
    }
}

// Convert GEMM weights to bf16 once per launch.
__global__ void k_cvt(const float* __restrict__ w1, const float* __restrict__ w2) {
    int i = blockIdx.x * blockDim.x + threadIdx.x;
    if (i < Cn * HID) {
        g_w1[i] = __float2bfloat16(w1[i]);
        g_w2[i] = __float2bfloat16(w2[i]);
    }
}

// ---------------------------------------------------------------------------
// Depthwise 7x7 conv + bias, NCHW in -> NHWC bf16 out. Block = (16 channels,
// one 8-row strip, one batch). Compute gated per 8x8 spatial group.
// Dynamic smem: 16 * 14 * 63 floats (padded halo tile).
// ---------------------------------------------------------------------------
__global__ __launch_bounds__(256) void k_conv(const float* __restrict__ x,
                                              const float* __restrict__ dww,
                                              const float* __restrict__ dwb) {
    extern __shared__ float sx[];                 // [16][14][63], plane=882
    const int ct = blockIdx.x;                    // 0..23 (channel tile)
    const int rt = blockIdx.y;                    // 0..6  (row strip)
    const int b  = blockIdx.z;

    __shared__ int actRow[7];
    if (threadIdx.x < 7) actRow[threadIdx.x] = g_active[b * 49 + rt * 7 + threadIdx.x];
    __syncthreads();
    int any = 0;
    #pragma unroll
    for (int i = 0; i < 7; i++) any |= actRow[i];
    if (!any) return;

    const int c0 = ct * 16;
    for (int idx = threadIdx.x; idx < 16 * 14 * 63; idx += 256) {
        int c = idx / (14 * 63);
        int rm = idx % (14 * 63);
        int ly = rm / 63, lx = rm % 63;
        int hy = rt * 8 + ly - 3;
        int wx = lx - 3;
        float v = 0.0f;
        if (hy >= 0 && hy < Hn && wx >= 0 && wx < Wn)
            v = x[((b * Cn + c0 + c) * Hn + hy) * Wn + wx];
        sx[c * 882 + ly * 63 + lx] = v;
    }

    const int cl = threadIdx.x & 15;
    const int wq = threadIdx.x >> 4;              // 0..15 (0..13 valid)
    const int cg = c0 + cl;
    float wt[49];
    #pragma unroll
    for (int k = 0; k < 49; k++) wt[k] = dww[cg * 49 + k];
    const float bias = dwb[cg];
    __syncthreads();

    if (wq < 14 && actRow[wq >> 1]) {
        const int w0 = wq * 4;
        for (int h = 0; h < 8; h++) {
            float a0 = bias, a1 = bias, a2 = bias, a3 = bias;
            #pragma unroll
            for (int dy = 0; dy < 7; dy++) {
                const float* r = &sx[cl * 882 + (h + dy) * 63 + w0];
                float win[10];
                #pragma unroll
                for (int m = 0; m < 10; m++) win[m] = r[m];
                #pragma unroll
                for (int dx = 0; dx < 7; dx++) {
                    float wv = wt[dy * 7 + dx];
                    a0 += win[dx]     * wv;
                    a1 += win[dx + 1] * wv;
                    a2 += win[dx + 2] * wv;
                    a3 += win[dx + 3] * wv;
                }
            }
            int hg = rt * 8 + h;
            int base = (b * 3136 + hg * 56 + w0) * Cn + cg;
            g_yconv[base         ] = __float2bfloat16(a0);
            g_yconv[base + Cn    ] = __float2bfloat16(a1);
            g_yconv[base + 2 * Cn] = __float2bfloat16(a2);
            g_yconv[base + 3 * Cn] = __float2bfloat16(a3);
        }
    }
}

// ---------------------------------------------------------------------------
// LayerNorm over C per token, active groups only, writes COMPACTED bf16 rows.
// 8 warps x 8 tokens per block (one 64-token group per block).
// ---------------------------------------------------------------------------
__global__ __launch_bounds__(256) void k_ln(const float* __restrict__ lnw,
                                            const float* __restrict__ lnb) {
    int g = blockIdx.x;
    int slot = g_slot[g];
    if (slot < 0) return;
    int b = g / 49, blk = g % 49, bh = blk / 7, bw = blk % 7;
    int wi = threadIdx.x >> 5, lane = threadIdx.x & 31;
    for (int j = 0; j < 8; j++) {
        int q = wi * 8 + j;
        int h = bh * 8 + (q >> 3), w = bw * 8 + (q & 7);
        int base = (b * 3136 + h * 56 + w) * Cn;
        float v[12];
        float s = 0.0f, ss = 0.0f;
        #pragma unroll
        for (int i = 0; i < 12; i++) {
            v[i] = __bfloat162float(g_yconv[base + lane + 32 * i]);
            s += v[i];
            ss += v[i] * v[i];
        }
        #pragma unroll
        for (int o = 16; o > 0; o >>= 1) {
            s  += __shfl_xor_sync(0xffffffff, s, o);
            ss += __shfl_xor_sync(0xffffffff, ss, o);
        }
        float mu = s * (1.0f / 384.0f);
        float var = ss * (1.0f / 384.0f) - mu * mu;
        float rstd = rsqrtf(var + EPSV);
        int ob = (slot * 64 + q) * Cn;
        #pragma unroll
        for (int i = 0; i < 12; i++) {
            int c = lane + 32 * i;
            float o = (v[i] - mu) * rstd * lnw[c] + lnb[c];
            g_xc[ob + c] = __float2bfloat16(o);
        }
    }
}

// Residual-only copy for inactive groups (out = x).
__global__ __launch_bounds__(256) void k_copy(const float* __restrict__ x,
                                              float* __restrict__ out) {
    int g = blockIdx.x;
    if (g_active[g]) return;
    int b = g / 49, blk = g % 49, bh = blk / 7, bw = blk % 7;
    for (int p = threadIdx.x; p < Cn * 8; p += 256) {
        int c = p >> 3, h8 = p & 7;
        int base = ((b * Cn + c) * Hn + bh * 8 + h8) * Wn + bw * 8;
        float4 v0 = *(const float4*)&x[base];
        float4 v1 = *(const float4*)&x[base + 4];
        *(float4*)&out[base] = v0;
        *(float4*)&out[base + 4] = v1;
    }
}

// ---------------------------------------------------------------------------
// bf16 GEMM, BM=128 BN=128 BK=32, 8 warps (4x2), mma.sync.m16n8k16.
// MODE 1: g_xc[rows,384] @ g_w1[384,1536] -> GELU(+b1) -> g_h (bf16)
// MODE 2: g_h[rows,1536] @ g_w2[1536,384] -> out = x + gamma*(acc+b2), NCHW
// ---------------------------------------------------------------------------
constexpr int ASTR = 56;    // halfs per A smem row (112B: conflict-free ldsm)
constexpr int BSTR = 136;   // halfs per B smem row (272B: conflict-free ldsm)

template <int KDIM, int LDA, int LDB, int MODE>
__global__ __launch_bounds__(256) void k_gemm(const float* __restrict__ bias,
                                              const float* __restrict__ gamma,
                                              const float* __restrict__ x,
                                              float* __restrict__ out) {
    const int validRows = g_count * 64;
    const int row0 = blockIdx.y * 128;
    if (row0 >= validRows) return;
    const int col0 = blockIdx.x * 128;

    const __nv_bfloat16* __restrict__ A  = (MODE == 1) ? g_xc : g_h;
    const __nv_bfloat16* __restrict__ Bg = (MODE == 1) ? g_w1 : g_w2;

    __shared__ __nv_bfloat16 As[128 * ASTR];
    __shared__ __nv_bfloat16 Bs[32 * BSTR];

    const int tid = threadIdx.x, lane = tid & 31, wid = tid >> 5;
    const int warpM = wid & 3, warpN = wid >> 2;

    float acc[2][8][4];
    #pragma unroll
    for (int i = 0; i < 2; i++)
        #pragma unroll
        for (int j = 0; j < 8; j++)
            #pragma unroll
            for (int k = 0; k < 4; k++) acc[i][j][k] = 0.0f;

    for (int k0 = 0; k0 < KDIM; k0 += 32) {
        #pragma unroll
        for (int it = 0; it < 2; it++) {                 // A: 128x32 bf16
            int idx = tid + it * 256;
            int r = idx >> 2, ch = idx & 3;
            uint4 v = make_uint4(0u, 0u, 0u, 0u);
            int gr = row0 + r;
            if (gr < validRows)
                v = *(const uint4*)&A[(long)gr * LDA + k0 + ch * 8];
            *(uint4*)&As[r * ASTR + ch * 8] = v;
        }
        #pragma unroll
        for (int it = 0; it < 2; it++) {                 // B: 32x128 bf16
            int idx = tid + it * 256;
            int kk = idx >> 4, nch = idx & 15;
            uint4 v = *(const uint4*)&Bg[(long)(k0 + kk) * LDB + col0 + nch * 8];
            *(uint4*)&Bs[kk * BSTR + nch * 8] = v;
        }
        __syncthreads();

        #pragma unroll
        for (int ks = 0; ks < 2; ks++) {
            const int kk = ks * 16;
            uint32_t a[2][4];
            #pragma unroll
            for (int mt = 0; mt < 2; mt++) {
                int rb = warpM * 32 + mt * 16;
                int quad = lane >> 3;
                int r = rb + (lane & 7) + (quad & 1) * 8;
                int c = kk + (quad >> 1) * 8;
                uint32_t addr = (uint32_t)__cvta_generic_to_shared(&As[r * ASTR + c]);
                asm volatile("ldmatrix.sync.aligned.m8n8.x4.shared.b16 {%0,%1,%2,%3}, [%4];"
                             : "=r"(a[mt][0]), "=r"(a[mt][1]), "=r"(a[mt][2]), "=r"(a[mt][3])
                             : "r"(addr));
            }
            uint32_t bq[8][2];
            #pragma unroll
            for (int nt = 0; nt < 8; nt++) {
                int ncol = warpN * 64 + nt * 8;
                int l2 = lane & 15;
                uint32_t addr = (uint32_t)__cvta_generic_to_shared(&Bs[(kk + l2) * BSTR + ncol]);
                asm volatile("ldmatrix.sync.aligned.m8n8.x2.trans.shared.b16 {%0,%1}, [%2];"
                             : "=r"(bq[nt][0]), "=r"(bq[nt][1]) : "r"(addr));
            }
            #pragma unroll
            for (int mt = 0; mt < 2; mt++)
                #pragma unroll
                for (int nt = 0; nt < 8; nt++) {
                    asm volatile(
                        "mma.sync.aligned.m16n8k16.row.col.f32.bf16.bf16.f32 "
                        "{%0,%1,%2,%3}, {%4,%5,%6,%7}, {%8,%9}, {%0,%1,%2,%3};"
                        : "+f"(acc[mt][nt][0]), "+f"(acc[mt][nt][1]),
                          "+f"(acc[mt][nt][2]), "+f"(acc[mt][nt][3])
                        : "r"(a[mt][0]), "r"(a[mt][1]), "r"(a[mt][2]), "r"(a[mt][3]),
                          "r"(bq[nt][0]), "r"(bq[nt][1]));
                }
        }
        __syncthreads();
    }

    const int t4 = lane & 3, gid = lane >> 2;
    #pragma unroll
    for (int mt = 0; mt < 2; mt++) {
        int rb = row0 + warpM * 32 + mt * 16 + gid;
        #pragma unroll
        for (int half = 0; half < 2; half++) {
            int r = rb + half * 8;
            if (r >= validRows) continue;
            if (MODE == 1) {
                #pragma unroll
                for (int nt = 0; nt < 8; nt++) {
                    int c = col0 + warpN * 64 + nt * 8 + t4 * 2;
                    float v0 = geluf(acc[mt][nt][half * 2 + 0] + bias[c]);
                    float v1 = geluf(acc[mt][nt][half * 2 + 1] + bias[c + 1]);
                    __nv_bfloat162 p;
                    p.x = __float2bfloat16(v0);
                    p.y = __float2bfloat16(v1);
                    *(__nv_bfloat162*)&g_h[(long)r * HID + c] = p;
                }
            } else {
                int e = g_list[r >> 6];
                int q = r & 63;
                int bb = e / 49, blk = e % 49;
                int h = (blk / 7) * 8 + (q >> 3);
                int w = (blk % 7) * 8 + (q & 7);
                #pragma unroll
                for (int nt = 0; nt < 8; nt++) {
                    int c = col0 + warpN * 64 + nt * 8 + t4 * 2;
                    int oi = ((bb * Cn + c) * Hn + h) * Wn + w;
                    float v0 = x[oi]        + gamma[c]     * (acc[mt][nt][half * 2 + 0] + bias[c]);
                    float v1 = x[oi + 3136] + gamma[c + 1] * (acc[mt][nt][half * 2 + 1] + bias[c + 1]);
                    out[oi] = v0;
                    out[oi + 3136] = v1;
                }
            }
        }
    }
}

// ---------------------------------------------------------------------------
extern "C" void kernel_launch(void* const* d_in, const int* in_sizes, int n_in,
                              void* d_out, int out_size) {
    const float* x   = (const float*)d_in[0];
    const unsigned char* mraw = (const unsigned char*)d_in[1];
    const float* dww = (const float*)d_in[2];
    const float* dwb = (const float*)d_in[3];
    const float* lnw = (const float*)d_in[4];
    const float* lnb = (const float*)d_in[5];
    const float* w1  = (const float*)d_in[6];
    const float* b1  = (const float*)d_in[7];
    const float* w2  = (const float*)d_in[8];
    const float* b2  = (const float*)d_in[9];
    const float* gm  = (const float*)d_in[10];
    float* out = (float*)d_out;

    const int convSmem = 16 * 14 * 63 * (int)sizeof(float);   // 56448 B
    cudaFuncSetAttribute(k_conv, cudaFuncAttributeMaxDynamicSharedMemorySize, convSmem);

    k_decode_mask<<<1, 256>>>(mraw);
    k_compact<<<1, 1024>>>();
    k_cvt<<<(Cn * HID + 255) / 256, 256>>>(w1, w2);
    k_conv<<<dim3(24, 7, 16), 256, convSmem>>>(x, dww, dwb);
    k_ln<<<NGRP, 256>>>(lnw, lnb);
    k_copy<<<NGRP, 256>>>(x, out);
    k_gemm<384, 384, 1536, 1><<<dim3(12, 392), 256>>>(b1, nullptr, nullptr, nullptr);
    k_gemm<1536, 1536, 384, 2><<<dim3(3, 392), 256>>>(b2, gm, x, out);
}